// round 3
// baseline (speedup 1.0000x reference)
#include <cuda_runtime.h>

// Column sums s[256] = sum over rows of x, accumulated by all blocks via
// atomicAdd. The LAST block (atomic counter) computes the 128-output GEMV,
// then zeroes g_colsum and resets the counter so CUDA-graph replays see
// identical initial state. No allocs, one kernel, one graph node.
__device__ float g_colsum[256];
__device__ unsigned int g_done_ctr = 0;

#define GRID   888          // 148 SMs * 6 CTAs  (42 regs -> 6 CTAs/SM fits)
#define BLOCK  256
#define UNROLL 8

__global__ void __launch_bounds__(BLOCK, 6) encoder_fused_kernel(
    const float4* __restrict__ x4, long n4,
    const float* __restrict__ W, float* __restrict__ out)
{
    const int tid = threadIdx.x;
    const long T = (long)GRID * BLOCK;           // total threads
    long idx = (long)blockIdx.x * BLOCK + tid;   // flat float4 index

    float4 acc = make_float4(0.f, 0.f, 0.f, 0.f);

    // ---- main stream: 8 independent LDG.128 in flight, streaming hint ----
    long i = idx;
    const long chunk = (long)UNROLL * T;
    for (; i + (UNROLL - 1) * T < n4; i += chunk) {
        float4 v0 = __ldcs(&x4[i + 0 * T]);
        float4 v1 = __ldcs(&x4[i + 1 * T]);
        float4 v2 = __ldcs(&x4[i + 2 * T]);
        float4 v3 = __ldcs(&x4[i + 3 * T]);
        float4 v4 = __ldcs(&x4[i + 4 * T]);
        float4 v5 = __ldcs(&x4[i + 5 * T]);
        float4 v6 = __ldcs(&x4[i + 6 * T]);
        float4 v7 = __ldcs(&x4[i + 7 * T]);
        acc.x += (v0.x + v1.x) + (v2.x + v3.x) + ((v4.x + v5.x) + (v6.x + v7.x));
        acc.y += (v0.y + v1.y) + (v2.y + v3.y) + ((v4.y + v5.y) + (v6.y + v7.y));
        acc.z += (v0.z + v1.z) + (v2.z + v3.z) + ((v4.z + v5.z) + (v6.z + v7.z));
        acc.w += (v0.w + v1.w) + (v2.w + v3.w) + ((v4.w + v5.w) + (v6.w + v7.w));
    }
    for (; i < n4; i += T) {
        float4 v = __ldcs(&x4[i]);
        acc.x += v.x; acc.y += v.y; acc.z += v.z; acc.w += v.w;
    }

    // ---- block-level combine: 4 threads share each column group ----
    // Column group of thread = (idx % 64); since T % 64 == 0 it is invariant
    // over the grid-stride walk, and within a block it equals tid % 64... but
    // blockIdx*BLOCK is a multiple of 64, so group(tid) = tid & 63. Threads
    // tid, tid+64, tid+128, tid+192 share a group.
    __shared__ float4 sh[BLOCK];
    sh[tid] = acc;
    __syncthreads();

    if (tid < 64) {
        float4 a = sh[tid];
        float4 b = sh[tid + 64];
        float4 d = sh[tid + 128];
        float4 e = sh[tid + 192];
        atomicAdd(&g_colsum[tid * 4 + 0], a.x + b.x + d.x + e.x);
        atomicAdd(&g_colsum[tid * 4 + 1], a.y + b.y + d.y + e.y);
        atomicAdd(&g_colsum[tid * 4 + 2], a.z + b.z + d.z + e.z);
        atomicAdd(&g_colsum[tid * 4 + 3], a.w + b.w + d.w + e.w);
    }

    // ---- last-block election ----
    __shared__ int is_last;
    __threadfence();
    __syncthreads();
    if (tid == 0) {
        unsigned int prev = atomicAdd(&g_done_ctr, 1u);
        is_last = (prev == GRID - 1) ? 1 : 0;
    }
    __syncthreads();
    if (!is_last) return;

    // ---- finalize (single block): gemv h[o] = dot(g_colsum, W[o]) ----
    __shared__ float s[256];
    s[tid] = g_colsum[tid];
    __syncthreads();

    // 8 warps * 16 outputs each = 128 outputs
    const int warp = tid >> 5;
    const int lane = tid & 31;
    for (int o = warp * 16; o < warp * 16 + 16; o++) {
        const float* Wrow = W + o * 256;
        float sum = 0.f;
        #pragma unroll
        for (int j = 0; j < 8; j++)
            sum += s[lane + 32 * j] * __ldg(&Wrow[lane + 32 * j]);
        #pragma unroll
        for (int off = 16; off; off >>= 1)
            sum += __shfl_xor_sync(0xFFFFFFFFu, sum, off);
        if (lane == 0) out[o] = sum;
    }
    __syncthreads();

    // ---- reset state for the next graph replay ----
    g_colsum[tid] = 0.0f;
    if (tid == 0) g_done_ctr = 0;
}

extern "C" void kernel_launch(void* const* d_in, const int* in_sizes, int n_in,
                              void* d_out, int out_size) {
    const float* x = (const float*)d_in[0];   // [rows, 256] fp32
    const float* W = (const float*)d_in[1];   // [128, 256] fp32
    float* out = (float*)d_out;               // [1, 128] fp32

    long n4 = (long)in_sizes[0] / 4;          // number of float4 elements

    encoder_fused_kernel<<<GRID, BLOCK>>>((const float4*)x, n4, W, out);
}

// round 4
// speedup vs baseline: 1.0577x; 1.0577x over previous
#include <cuda_runtime.h>

__device__ float g_colsum[256];
__device__ unsigned int g_done_ctr = 0;

#define GRID   592          // 148 SMs * 4 CTAs (best measured concurrency)
#define BLOCK  256
#define NWARPS (GRID * (BLOCK / 32))   // 4736 warps total

__global__ void __launch_bounds__(BLOCK) encoder_fused_kernel(
    const float4* __restrict__ x4, long n4,
    const float* __restrict__ W, float* __restrict__ out)
{
    const int tid  = threadIdx.x;
    const int lane = tid & 31;
    const int wid_global = blockIdx.x * (BLOCK / 32) + (tid >> 5);

    // Contiguous per-warp chunk, rounded up to a multiple of 64 float4
    // (so every chunk base is row-pair aligned: base % 64 == 0).
    const long ch_raw = (n4 + NWARPS - 1) / NWARPS;
    const long CH = (ch_raw + 63) & ~63L;

    long base = (long)wid_global * CH;
    long end  = base + CH; if (end > n4) end = n4;

    // Thread walks base+lane, base+lane+32, ... Column group of index i is
    // (i & 63); base % 64 == 0, so even steps hit group `lane`, odd steps
    // hit group `lane + 32`. Two accumulators track the two groups.
    float4 accA = make_float4(0.f, 0.f, 0.f, 0.f);  // group lane
    float4 accB = make_float4(0.f, 0.f, 0.f, 0.f);  // group lane + 32

    long i = base + lane;
    // 8 loads in flight; warp covers 4 KB sequentially per iteration.
    for (; i + 224 < end; i += 256) {
        float4 v0 = __ldcs(&x4[i +   0]);
        float4 v1 = __ldcs(&x4[i +  32]);
        float4 v2 = __ldcs(&x4[i +  64]);
        float4 v3 = __ldcs(&x4[i +  96]);
        float4 v4 = __ldcs(&x4[i + 128]);
        float4 v5 = __ldcs(&x4[i + 160]);
        float4 v6 = __ldcs(&x4[i + 192]);
        float4 v7 = __ldcs(&x4[i + 224]);
        accA.x += (v0.x + v2.x) + (v4.x + v6.x);
        accA.y += (v0.y + v2.y) + (v4.y + v6.y);
        accA.z += (v0.z + v2.z) + (v4.z + v6.z);
        accA.w += (v0.w + v2.w) + (v4.w + v6.w);
        accB.x += (v1.x + v3.x) + (v5.x + v7.x);
        accB.y += (v1.y + v3.y) + (v5.y + v7.y);
        accB.z += (v1.z + v3.z) + (v5.z + v7.z);
        accB.w += (v1.w + v3.w) + (v5.w + v7.w);
    }
    for (; i < end; i += 32) {
        float4 v = __ldcs(&x4[i]);
        if (((i >> 5) & 1) == 0) {
            accA.x += v.x; accA.y += v.y; accA.z += v.z; accA.w += v.w;
        } else {
            accB.x += v.x; accB.y += v.y; accB.z += v.z; accB.w += v.w;
        }
    }

    // ---- block combine via smem atomics (once per CTA, cheap) ----
    __shared__ float sh[256];
    if (tid < 256) sh[tid] = 0.f;   // BLOCK == 256
    __syncthreads();
    atomicAdd(&sh[4 * lane + 0], accA.x);
    atomicAdd(&sh[4 * lane + 1], accA.y);
    atomicAdd(&sh[4 * lane + 2], accA.z);
    atomicAdd(&sh[4 * lane + 3], accA.w);
    atomicAdd(&sh[128 + 4 * lane + 0], accB.x);
    atomicAdd(&sh[128 + 4 * lane + 1], accB.y);
    atomicAdd(&sh[128 + 4 * lane + 2], accB.z);
    atomicAdd(&sh[128 + 4 * lane + 3], accB.w);
    __syncthreads();

    if (tid < 64) {
        atomicAdd(&g_colsum[tid * 4 + 0], sh[tid * 4 + 0]);
        atomicAdd(&g_colsum[tid * 4 + 1], sh[tid * 4 + 1]);
        atomicAdd(&g_colsum[tid * 4 + 2], sh[tid * 4 + 2]);
        atomicAdd(&g_colsum[tid * 4 + 3], sh[tid * 4 + 3]);
    }

    // ---- last-block election ----
    __shared__ int is_last;
    __threadfence();
    __syncthreads();
    if (tid == 0) {
        unsigned int prev = atomicAdd(&g_done_ctr, 1u);
        is_last = (prev == GRID - 1) ? 1 : 0;
    }
    __syncthreads();
    if (!is_last) return;

    // ---- finalize: gemv h[o] = dot(g_colsum, W[o]) ----
    __shared__ float s[256];
    s[tid] = g_colsum[tid];
    __syncthreads();

    const int warp = tid >> 5;
    for (int o = warp * 16; o < warp * 16 + 16; o++) {
        const float* Wrow = W + o * 256;
        float sum = 0.f;
        #pragma unroll
        for (int j = 0; j < 8; j++)
            sum += s[lane + 32 * j] * __ldg(&Wrow[lane + 32 * j]);
        #pragma unroll
        for (int off = 16; off; off >>= 1)
            sum += __shfl_xor_sync(0xFFFFFFFFu, sum, off);
        if (lane == 0) out[o] = sum;
    }
    __syncthreads();

    // ---- reset state for next graph replay ----
    g_colsum[tid] = 0.0f;
    if (tid == 0) g_done_ctr = 0;
}

extern "C" void kernel_launch(void* const* d_in, const int* in_sizes, int n_in,
                              void* d_out, int out_size) {
    const float* x = (const float*)d_in[0];   // [rows, 256] fp32
    const float* W = (const float*)d_in[1];   // [128, 256] fp32
    float* out = (float*)d_out;               // [1, 128] fp32

    long n4 = (long)in_sizes[0] / 4;          // number of float4 elements

    encoder_fused_kernel<<<GRID, BLOCK>>>((const float4*)x, n4, W, out);
}

// round 5
// speedup vs baseline: 1.0984x; 1.0385x over previous
#include <cuda_runtime.h>
#include <cstdint>

__device__ float g_colsum[256];
__device__ unsigned int g_done_ctr = 0;

#define GRID    592           // 148 SMs * 4 CTAs
#define BLOCK   256
#define STAGES  4
#define STAGE_F4 640          // float4 per stage (multiple of 64)
#define STAGE_BYTES (STAGE_F4 * 16)   // 10240 B

__device__ __forceinline__ uint32_t smem_u32(const void* p) {
    uint32_t a;
    asm("{ .reg .u64 t; cvta.to.shared.u64 t, %1; cvt.u32.u64 %0, t; }"
        : "=r"(a) : "l"(p));
    return a;
}

__device__ __forceinline__ void mbar_init(uint32_t mbar, uint32_t count) {
    asm volatile("mbarrier.init.shared.b64 [%0], %1;" :: "r"(mbar), "r"(count) : "memory");
}
__device__ __forceinline__ void mbar_expect_tx(uint32_t mbar, uint32_t bytes) {
    asm volatile("mbarrier.arrive.expect_tx.shared.b64 _, [%0], %1;"
                 :: "r"(mbar), "r"(bytes) : "memory");
}
__device__ __forceinline__ void mbar_wait(uint32_t mbar, uint32_t parity) {
    asm volatile(
        "{\n\t.reg .pred P;\n"
        "WAIT_%=:\n\t"
        "mbarrier.try_wait.parity.acquire.cta.shared::cta.b64 P, [%0], %1, 0x989680;\n\t"
        "@P bra.uni DONE_%=;\n\t"
        "bra.uni WAIT_%=;\n"
        "DONE_%=:\n\t}"
        :: "r"(mbar), "r"(parity) : "memory");
}
__device__ __forceinline__ void tma_bulk_load(uint32_t dst_smem, const void* src,
                                              uint32_t bytes, uint32_t mbar) {
    asm volatile(
        "cp.async.bulk.shared::cluster.global.mbarrier::complete_tx::bytes "
        "[%0], [%1], %2, [%3];"
        :: "r"(dst_smem), "l"(src), "r"(bytes), "r"(mbar) : "memory");
}

__global__ void __launch_bounds__(BLOCK) encoder_tma_kernel(
    const float4* __restrict__ x4, long n4,
    const float* __restrict__ W, float* __restrict__ out)
{
    __shared__ __align__(16) float4 buf[STAGES][STAGE_F4];   // 40 KB
    __shared__ __align__(8)  unsigned long long mbar[STAGES];
    __shared__ float4 shv[BLOCK];                            //  4 KB
    __shared__ float  sgemv[256];                            //  1 KB

    const int tid = threadIdx.x;
    const long nchunks = (n4 + STAGE_F4 - 1) / STAGE_F4;

    if (tid == 0) {
        #pragma unroll
        for (int s = 0; s < STAGES; s++) mbar_init(smem_u32(&mbar[s]), 1);
    }
    __syncthreads();

    // ---- prologue: issue first STAGES copies ----
    if (tid == 0) {
        #pragma unroll
        for (int s = 0; s < STAGES; s++) {
            long chunk = blockIdx.x + (long)s * GRID;
            if (chunk < nchunks) {
                long base = chunk * STAGE_F4;
                uint32_t cnt = (uint32_t)((n4 - base < STAGE_F4) ? (n4 - base) : STAGE_F4);
                uint32_t bytes = cnt * 16u;
                uint32_t mb = smem_u32(&mbar[s]);
                mbar_expect_tx(mb, bytes);
                tma_bulk_load(smem_u32(&buf[s][0]), x4 + base, bytes, mb);
            }
        }
    }

    // ---- main pipeline ----
    float4 acc = make_float4(0.f, 0.f, 0.f, 0.f);  // column group tid & 63
    long it = 0;
    for (long chunk = blockIdx.x; chunk < nchunks; chunk += GRID, it++) {
        const int s = (int)(it & (STAGES - 1));
        const uint32_t parity = (uint32_t)((it >> 2) & 1);
        mbar_wait(smem_u32(&mbar[s]), parity);

        long base = chunk * STAGE_F4;
        int cnt = (int)((n4 - base < STAGE_F4) ? (n4 - base) : STAGE_F4);
        // j = tid + k*256; 256 % 64 == 0 and base % 64 == 0, so every element
        // this thread touches belongs to column group tid & 63.
        for (int j = tid; j < cnt; j += BLOCK) {
            float4 v = buf[s][j];
            acc.x += v.x; acc.y += v.y; acc.z += v.z; acc.w += v.w;
        }
        __syncthreads();   // whole CTA done reading stage s

        if (tid == 0) {
            long nchunk = chunk + (long)STAGES * GRID;
            if (nchunk < nchunks) {
                long nbase = nchunk * STAGE_F4;
                uint32_t ncnt = (uint32_t)((n4 - nbase < STAGE_F4) ? (n4 - nbase) : STAGE_F4);
                uint32_t bytes = ncnt * 16u;
                uint32_t mb = smem_u32(&mbar[s]);
                mbar_expect_tx(mb, bytes);
                tma_bulk_load(smem_u32(&buf[s][0]), x4 + nbase, bytes, mb);
            }
        }
    }

    // ---- block combine: threads tid, tid+64, tid+128, tid+192 share group ----
    shv[tid] = acc;
    __syncthreads();
    if (tid < 64) {
        float4 a = shv[tid];
        float4 b = shv[tid + 64];
        float4 d = shv[tid + 128];
        float4 e = shv[tid + 192];
        atomicAdd(&g_colsum[tid * 4 + 0], a.x + b.x + d.x + e.x);
        atomicAdd(&g_colsum[tid * 4 + 1], a.y + b.y + d.y + e.y);
        atomicAdd(&g_colsum[tid * 4 + 2], a.z + b.z + d.z + e.z);
        atomicAdd(&g_colsum[tid * 4 + 3], a.w + b.w + d.w + e.w);
    }

    // ---- last-block election ----
    __shared__ int is_last;
    __threadfence();
    __syncthreads();
    if (tid == 0) {
        unsigned int prev = atomicAdd(&g_done_ctr, 1u);
        is_last = (prev == GRID - 1) ? 1 : 0;
    }
    __syncthreads();
    if (!is_last) return;

    // ---- finalize: gemv h[o] = dot(g_colsum, W[o]) ----
    sgemv[tid] = g_colsum[tid];
    __syncthreads();

    const int warp = tid >> 5;
    const int lane = tid & 31;
    for (int o = warp * 16; o < warp * 16 + 16; o++) {
        const float* Wrow = W + o * 256;
        float sum = 0.f;
        #pragma unroll
        for (int j = 0; j < 8; j++)
            sum += sgemv[lane + 32 * j] * __ldg(&Wrow[lane + 32 * j]);
        #pragma unroll
        for (int off = 16; off; off >>= 1)
            sum += __shfl_xor_sync(0xFFFFFFFFu, sum, off);
        if (lane == 0) out[o] = sum;
    }
    __syncthreads();

    // ---- reset device state for next graph replay ----
    g_colsum[tid] = 0.0f;
    if (tid == 0) g_done_ctr = 0;
}

extern "C" void kernel_launch(void* const* d_in, const int* in_sizes, int n_in,
                              void* d_out, int out_size) {
    const float* x = (const float*)d_in[0];   // [rows, 256] fp32
    const float* W = (const float*)d_in[1];   // [128, 256] fp32
    float* out = (float*)d_out;               // [1, 128] fp32

    long n4 = (long)in_sizes[0] / 4;          // float4 element count

    encoder_tma_kernel<<<GRID, BLOCK>>>((const float4*)x, n4, W, out);
}